// round 14
// baseline (speedup 1.0000x reference)
#include <cuda_runtime.h>
#include <cuda_fp16.h>
#include <math.h>
#include <stdint.h>

// ---------------- problem dims ----------------
#define BDIM 4
#define TDIM 2048
#define DDIM 512
#define EDIM 4
#define CDIM 1024
#define HEDIM 512
#define ODIM 512
#define ECDIM 4096

typedef __half f16;

// ---------------- operand storage (no cudaMalloc allowed) ----------------
__device__ f16 g_dm [(size_t)BDIM * TDIM * ECDIM];   // dmask (native layout, f16)
__device__ f16 g_cmb[(size_t)BDIM * TDIM * ECDIM];   // combine
__device__ f16 g_x  [(size_t)BDIM * TDIM * DDIM];
__device__ f16 g_w1 [(size_t)EDIM * DDIM * HEDIM];
__device__ f16 g_w2 [(size_t)EDIM * HEDIM * ODIM];
__device__ f16 g_xd [(size_t)BDIM * ECDIM * DDIM];
__device__ f16 g_h  [(size_t)BDIM * ECDIM * HEDIM];
__device__ f16 g_y  [(size_t)BDIM * ECDIM * ODIM];

// ---------------- helpers ----------------
__device__ __forceinline__ uint32_t pack_h2(float a, float b) {
    __half2 p = __floats2half2_rn(a, b);
    return *reinterpret_cast<uint32_t*>(&p);
}

// ---------------- conversion kernel (MLP-4 grid-stride) ----------------
__global__ void conv_ew(const float* __restrict__ s, f16* __restrict__ d,
                        long long n4) {
    const long long stride = (long long)gridDim.x * blockDim.x;
    long long i = (long long)blockIdx.x * blockDim.x + threadIdx.x;
    const float4* __restrict__ src = reinterpret_cast<const float4*>(s);
    uint2* __restrict__ dst = reinterpret_cast<uint2*>(d);
    for (; i + 3 * stride < n4; i += 4 * stride) {
        float4 v0 = src[i];
        float4 v1 = src[i + stride];
        float4 v2 = src[i + 2 * stride];
        float4 v3 = src[i + 3 * stride];
        uint2 h0, h1, h2, h3;
        h0.x = pack_h2(v0.x, v0.y); h0.y = pack_h2(v0.z, v0.w);
        h1.x = pack_h2(v1.x, v1.y); h1.y = pack_h2(v1.z, v1.w);
        h2.x = pack_h2(v2.x, v2.y); h2.y = pack_h2(v2.z, v2.w);
        h3.x = pack_h2(v3.x, v3.y); h3.y = pack_h2(v3.z, v3.w);
        dst[i] = h0;
        dst[i + stride] = h1;
        dst[i + 2 * stride] = h2;
        dst[i + 3 * stride] = h3;
    }
    for (; i < n4; i += stride) {
        float4 v = src[i];
        uint2 h;
        h.x = pack_h2(v.x, v.y); h.y = pack_h2(v.z, v.w);
        dst[i] = h;
    }
}
static inline unsigned conv_grid(long long n4) {
    long long g = (n4 + 4LL * 256 - 1) / (4LL * 256);
    if (g > 65535) g = 65535;
    return (unsigned)g;
}

// ---------------- GEMM tile config ----------------
constexpr int BM = 128, BN = 128, BK = 64;
constexpr int THREADS = 256;
constexpr int OFF_B  = 16384;                // A tile 16 KB
constexpr int STAGE  = 32768;                // + B tile 16 KB
constexpr int NSTG   = 3;
constexpr int SMEM_TOTAL = NSTG * STAGE;     // 96 KB -> 2 CTAs/SM

// A row-major tile: 128 rows x 128B (64 k x f16), swizzled
__device__ __forceinline__ int a_off(int m, int kc) {   // kc 0..7
    return m * 128 + ((kc ^ (m & 7)) << 4);
}
// B / ATR-A tile: 64 k-rows x 256B (128 elems), swizzled
__device__ __forceinline__ int b_off(int k, int nc) {   // nc 0..15
    return k * 256 + ((nc ^ (k & 7)) << 4);
}
__device__ __forceinline__ uint32_t smem_u32(const void* p) {
    uint32_t a;
    asm("{ .reg .u64 t; cvta.to.shared.u64 t, %1; cvt.u32.u64 %0, t; }"
        : "=r"(a) : "l"(p));
    return a;
}
__device__ __forceinline__ void ldsm4(uint32_t* r, uint32_t addr) {
    asm volatile("ldmatrix.sync.aligned.m8n8.x4.shared.b16 {%0,%1,%2,%3}, [%4];"
                 : "=r"(r[0]), "=r"(r[1]), "=r"(r[2]), "=r"(r[3]) : "r"(addr));
}
__device__ __forceinline__ void ldsm4t(uint32_t* r, uint32_t addr) {
    asm volatile("ldmatrix.sync.aligned.m8n8.x4.trans.shared.b16 {%0,%1,%2,%3}, [%4];"
                 : "=r"(r[0]), "=r"(r[1]), "=r"(r[2]), "=r"(r[3]) : "r"(addr));
}
__device__ __forceinline__ void mma_f16(float* d, const uint32_t* a, const uint32_t* b) {
    asm volatile(
        "mma.sync.aligned.m16n8k16.row.col.f32.f16.f16.f32 "
        "{%0,%1,%2,%3}, {%4,%5,%6,%7}, {%8,%9}, {%0,%1,%2,%3};"
        : "+f"(d[0]), "+f"(d[1]), "+f"(d[2]), "+f"(d[3])
        : "r"(a[0]), "r"(a[1]), "r"(a[2]), "r"(a[3]), "r"(b[0]), "r"(b[1]));
}
__device__ __forceinline__ void cp16(uint32_t dst, const void* src) {
    asm volatile("cp.async.cg.shared.global [%0], [%1], 16;" :: "r"(dst), "l"(src));
}
__device__ __forceinline__ void cp_commit() {
    asm volatile("cp.async.commit_group;" ::: "memory");
}
template<int N>
__device__ __forceinline__ void cp_wait() {
    asm volatile("cp.async.wait_group %0;" :: "n"(N) : "memory");
}

// ---------------- main GEMM kernel ----------------
// CTA 128x128, BK=64, warp tile 64x32, 2 CTAs/SM, fp16 in / fp32 accum.
// A-fragment double-buffered across the 4 kh sub-steps.
// ATR=1: A stored K-major [k][m] (dispatch mask); smem uses B-style layout + ldsm.trans.
// Two-level z indexing: off = (z/zMod)*s1 + (z%zMod)*s2; bias indexed by zr.
// OUTM: 0 = fp32 out, 2 = single f16 out.
template<int ATR, int OUTM, bool GELU_, bool BIAS_>
__global__ __launch_bounds__(THREADS, 2)
void moe_gemm(const f16* __restrict__ Ab, const f16* __restrict__ Bb,
              float* __restrict__ Cf, f16* __restrict__ Ch,
              const float* __restrict__ biasBase,
              int lda, int ldb, int ldc, int KT, int zMod,
              long long sA1, long long sA2, long long sB1, long long sB2,
              long long sC1, long long sC2, long long sBias2)
{
    extern __shared__ char smem[];
    const int tid  = threadIdx.x;
    const int lane = tid & 31;
    const int wid  = tid >> 5;
    const int wm   = (wid & 1) * 64;
    const int wn   = (wid >> 1) * 32;

    const int z = blockIdx.z;
    const int zq = z / zMod, zr = z % zMod;
    const f16* A = Ab + zq * sA1 + zr * sA2;
    const f16* B = Bb + zq * sB1 + zr * sB2;
    const long long coff = zq * sC1 + zr * sC2;
    const float* bias = BIAS_ ? biasBase + zr * sBias2 : nullptr;

    const int m0 = blockIdx.y * BM;
    const int n0 = blockIdx.x * BN;
    const uint32_t sbase = smem_u32(smem);

    float acc[4][4][4];
#pragma unroll
    for (int i = 0; i < 4; i++)
#pragma unroll
        for (int j = 0; j < 4; j++)
#pragma unroll
            for (int c = 0; c < 4; c++) acc[i][j][c] = 0.f;

    auto issue = [&](int it) {
        if (it < KT) {
            const uint32_t st = sbase + (it % NSTG) * STAGE;
            const int k0 = it * BK;
#pragma unroll
            for (int i = 0; i < 4; i++) {
                int c = tid + i * THREADS;          // 1024 chunks A
                if (ATR) {
                    int k = c >> 4, mc = c & 15;    // gmem row k, 16B m-chunk
                    cp16(st + b_off(k, mc),
                         A + (size_t)(k0 + k) * lda + m0 + mc * 8);
                } else {
                    int m = c >> 3, kc = c & 7;
                    cp16(st + a_off(m, kc),
                         A + (size_t)(m0 + m) * lda + k0 + kc * 8);
                }
            }
#pragma unroll
            for (int i = 0; i < 4; i++) {
                int c = tid + i * THREADS;          // 1024 chunks B
                int k = c >> 4, nc = c & 15;
                cp16(st + OFF_B + b_off(k, nc),
                     B + (size_t)(k0 + k) * ldb + n0 + nc * 8);
            }
        }
        cp_commit();
    };

    issue(0); issue(1);

    for (int it = 0; it < KT; ++it) {
        cp_wait<1>();
        __syncthreads();
        issue(it + 2);

        const uint32_t cur = sbase + (it % NSTG) * STAGE;

        auto loadA = [&](int kh, uint32_t (*ar)[4]) {
#pragma unroll
            for (int mf = 0; mf < 4; mf++) {
                if (ATR) {
                    int k = kh * 16 + (lane >> 4) * 8 + (lane & 7);
                    int mchunk = ((wm + mf * 16) >> 3) + ((lane >> 3) & 1);
                    ldsm4t(ar[mf], cur + b_off(k, mchunk));
                } else {
                    int row = wm + mf * 16 + (lane & 15);
                    int chunk = kh * 2 + (lane >> 4);
                    ldsm4(ar[mf], cur + a_off(row, chunk));
                }
            }
        };

        uint32_t arbuf[2][4][4];
        loadA(0, arbuf[0]);
#pragma unroll
        for (int kh = 0; kh < 4; kh++) {
            uint32_t br[2][4];
#pragma unroll
            for (int nb = 0; nb < 2; nb++) {
                int k = kh * 16 + ((lane >> 3) & 1) * 8 + (lane & 7);
                int nchunk = ((wn + nb * 16) >> 3) + (lane >> 4);
                ldsm4t(br[nb], cur + OFF_B + b_off(k, nchunk));
            }
            if (kh < 3) loadA(kh + 1, arbuf[(kh + 1) & 1]);
            uint32_t (*ar)[4] = arbuf[kh & 1];
#pragma unroll
            for (int mf = 0; mf < 4; mf++)
#pragma unroll
                for (int nf = 0; nf < 4; nf++)
                    mma_f16(acc[mf][nf], ar[mf], &br[nf >> 1][(nf & 1) * 2]);
        }
    }

    // ---- epilogue ----
    const int g = lane >> 2, t = lane & 3;
#pragma unroll
    for (int mf = 0; mf < 4; mf++) {
#pragma unroll
        for (int nf = 0; nf < 4; nf++) {
            int row = m0 + wm + mf * 16 + g;
            int col = n0 + wn + nf * 8 + t * 2;
            float v0 = acc[mf][nf][0], v1 = acc[mf][nf][1];
            float v2 = acc[mf][nf][2], v3 = acc[mf][nf][3];
            if (BIAS_) {
                float2 bv = *reinterpret_cast<const float2*>(bias + col);
                v0 += bv.x; v1 += bv.y; v2 += bv.x; v3 += bv.y;
            }
            if (GELU_) {
                v0 = 0.5f * v0 * (1.0f + erff(v0 * 0.70710678118654752f));
                v1 = 0.5f * v1 * (1.0f + erff(v1 * 0.70710678118654752f));
                v2 = 0.5f * v2 * (1.0f + erff(v2 * 0.70710678118654752f));
                v3 = 0.5f * v3 * (1.0f + erff(v3 * 0.70710678118654752f));
            }
            size_t o0 = (size_t)(coff + (size_t)row * ldc + col);
            size_t o1 = (size_t)(coff + (size_t)(row + 8) * ldc + col);
            if (OUTM == 0) {
                *reinterpret_cast<float2*>(Cf + o0) = make_float2(v0, v1);
                *reinterpret_cast<float2*>(Cf + o1) = make_float2(v2, v3);
            } else {
                *reinterpret_cast<uint32_t*>(Ch + o0) = pack_h2(v0, v1);
                *reinterpret_cast<uint32_t*>(Ch + o1) = pack_h2(v2, v3);
            }
        }
    }
}

// ---------------- launcher ----------------
extern "C" void kernel_launch(void* const* d_in, const int* in_sizes, int n_in,
                              void* d_out, int out_size)
{
    const float* x     = (const float*)d_in[0];
    const float* dmask = (const float*)d_in[1];
    const float* comb  = (const float*)d_in[2];
    const float* w1    = (const float*)d_in[3];
    const float* b1    = (const float*)d_in[4];
    const float* w2f   = (const float*)d_in[5];
    const float* b2    = (const float*)d_in[6];
    float* out = (float*)d_out;

    f16 *dm, *cmb, *xs, *w1s, *w2s, *xd, *hh, *yy;
    cudaGetSymbolAddress((void**)&dm,  g_dm);
    cudaGetSymbolAddress((void**)&cmb, g_cmb);
    cudaGetSymbolAddress((void**)&xs,  g_x);
    cudaGetSymbolAddress((void**)&w1s, g_w1);
    cudaGetSymbolAddress((void**)&w2s, g_w2);
    cudaGetSymbolAddress((void**)&xd,  g_xd);
    cudaGetSymbolAddress((void**)&hh,  g_h);
    cudaGetSymbolAddress((void**)&yy,  g_y);

    cudaFuncSetAttribute(moe_gemm<1, 2, false, false>,
                         cudaFuncAttributeMaxDynamicSharedMemorySize, SMEM_TOTAL);
    cudaFuncSetAttribute(moe_gemm<0, 2, true,  true>,
                         cudaFuncAttributeMaxDynamicSharedMemorySize, SMEM_TOTAL);
    cudaFuncSetAttribute(moe_gemm<0, 2, false, false>,
                         cudaFuncAttributeMaxDynamicSharedMemorySize, SMEM_TOTAL);
    cudaFuncSetAttribute(moe_gemm<0, 0, false, true>,
                         cudaFuncAttributeMaxDynamicSharedMemorySize, SMEM_TOTAL);

    // ---- conversions (elementwise fp16, MLP-4) ----
    {
        long long n4 = (long long)BDIM * TDIM * ECDIM / 4;
        conv_ew<<<conv_grid(n4), 256>>>(dmask, dm, n4);
        conv_ew<<<conv_grid(n4), 256>>>(comb, cmb, n4);
    }
    {
        long long n4 = (long long)BDIM * TDIM * DDIM / 4;
        conv_ew<<<conv_grid(n4), 256>>>(x, xs, n4);
    }
    {
        long long n4 = (long long)EDIM * DDIM * HEDIM / 4;
        conv_ew<<<conv_grid(n4), 256>>>(w1, w1s, n4);
        conv_ew<<<conv_grid(n4), 256>>>(w2f, w2s, n4);
    }

    // ---- K1: xd[b][EC][D] = dmask_b^T[EC][T] @ x[b][T][D]  (ATR) ----
    moe_gemm<1, 2, false, false>
        <<<dim3(DDIM / BN, ECDIM / BM, BDIM), THREADS, SMEM_TOTAL>>>(
        dm, xs, nullptr, xd, nullptr,
        ECDIM, DDIM, DDIM, TDIM / BK, /*zMod*/ 1,
        (long long)TDIM * ECDIM, 0, (long long)TDIM * DDIM, 0,
        (long long)ECDIM * DDIM, 0, 0);

    // ---- K2: h[b,e][C][HE] = gelu(xd_{b,e}[C][D] @ w1_e[D][HE] + b1_e) ----
    moe_gemm<0, 2, true, true>
        <<<dim3(HEDIM / BN, CDIM / BM, BDIM * EDIM), THREADS, SMEM_TOTAL>>>(
        xd, w1s, nullptr, hh, b1,
        DDIM, HEDIM, HEDIM, DDIM / BK, /*zMod*/ EDIM,
        (long long)EDIM * CDIM * DDIM, (long long)CDIM * DDIM,
        0, (long long)DDIM * HEDIM,
        (long long)EDIM * CDIM * HEDIM, (long long)CDIM * HEDIM,
        (long long)HEDIM);

    // ---- K3: y[b,e][C][O] = h_{b,e}[C][HE] @ w2_e[HE][O] ----
    moe_gemm<0, 2, false, false>
        <<<dim3(ODIM / BN, CDIM / BM, BDIM * EDIM), THREADS, SMEM_TOTAL>>>(
        hh, w2s, nullptr, yy, nullptr,
        HEDIM, ODIM, ODIM, HEDIM / BK, /*zMod*/ EDIM,
        (long long)EDIM * CDIM * HEDIM, (long long)CDIM * HEDIM,
        0, (long long)HEDIM * ODIM,
        (long long)EDIM * CDIM * ODIM, (long long)CDIM * ODIM,
        0);

    // ---- K4: out[b][T][O] = comb[b][T][EC] @ y[b][EC][O] + b2 ----
    moe_gemm<0, 0, false, true>
        <<<dim3(ODIM / BN, TDIM / BM, BDIM), THREADS, SMEM_TOTAL>>>(
        cmb, yy, out, nullptr, b2,
        ECDIM, ODIM, ODIM, ECDIM / BK, /*zMod*/ 1,
        (long long)TDIM * ECDIM, 0, (long long)ECDIM * ODIM, 0,
        (long long)TDIM * ODIM, 0, 0);
}

// round 15
// speedup vs baseline: 1.0500x; 1.0500x over previous
#include <cuda_runtime.h>
#include <cuda_fp16.h>
#include <math.h>
#include <stdint.h>

// ---------------- problem dims ----------------
#define BDIM 4
#define TDIM 2048
#define DDIM 512
#define EDIM 4
#define CDIM 1024
#define HEDIM 512
#define ODIM 512
#define ECDIM 4096

typedef __half f16;

// ---------------- operand storage (no cudaMalloc allowed) ----------------
__device__ f16 g_dm [(size_t)BDIM * TDIM * ECDIM];   // dmask (native layout, f16)
__device__ f16 g_cmb[(size_t)BDIM * TDIM * ECDIM];   // combine
__device__ f16 g_x  [(size_t)BDIM * TDIM * DDIM];
__device__ f16 g_w1 [(size_t)EDIM * DDIM * HEDIM];
__device__ f16 g_w2 [(size_t)EDIM * HEDIM * ODIM];
__device__ f16 g_xd [(size_t)BDIM * ECDIM * DDIM];
__device__ f16 g_h  [(size_t)BDIM * ECDIM * HEDIM];
__device__ f16 g_y  [(size_t)BDIM * ECDIM * ODIM];

// ---------------- helpers ----------------
__device__ __forceinline__ uint32_t pack_h2(float a, float b) {
    __half2 p = __floats2half2_rn(a, b);
    return *reinterpret_cast<uint32_t*>(&p);
}

// ---------------- conversion kernel (MLP-2 contiguous: 2 adjacent float4/thread) ----
__global__ void conv_ew(const float* __restrict__ s, f16* __restrict__ d,
                        long long n4) {
    long long i = 2 * ((long long)blockIdx.x * blockDim.x + threadIdx.x);
    if (i + 1 < n4) {
        const float4* __restrict__ src = reinterpret_cast<const float4*>(s);
        uint2* __restrict__ dst = reinterpret_cast<uint2*>(d);
        float4 v0 = src[i];
        float4 v1 = src[i + 1];
        uint2 h0, h1;
        h0.x = pack_h2(v0.x, v0.y); h0.y = pack_h2(v0.z, v0.w);
        h1.x = pack_h2(v1.x, v1.y); h1.y = pack_h2(v1.z, v1.w);
        dst[i] = h0;
        dst[i + 1] = h1;
    } else if (i < n4) {
        float4 v = reinterpret_cast<const float4*>(s)[i];
        uint2 h;
        h.x = pack_h2(v.x, v.y); h.y = pack_h2(v.z, v.w);
        reinterpret_cast<uint2*>(d)[i] = h;
    }
}
static inline unsigned conv_grid(long long n4) {
    return (unsigned)((n4 / 2 + 255) / 256);
}

// ---------------- GEMM tile config ----------------
constexpr int BM = 128, BN = 128, BK = 64;
constexpr int THREADS = 256;
constexpr int OFF_B  = 16384;                // A tile 16 KB
constexpr int STAGE  = 32768;                // + B tile 16 KB
constexpr int NSTG   = 3;
constexpr int SMEM_TOTAL = NSTG * STAGE;     // 96 KB -> 2 CTAs/SM

// A row-major tile: 128 rows x 128B (64 k x f16), swizzled
__device__ __forceinline__ int a_off(int m, int kc) {   // kc 0..7
    return m * 128 + ((kc ^ (m & 7)) << 4);
}
// B / ATR-A tile: 64 k-rows x 256B (128 elems), swizzled
__device__ __forceinline__ int b_off(int k, int nc) {   // nc 0..15
    return k * 256 + ((nc ^ (k & 7)) << 4);
}
__device__ __forceinline__ uint32_t smem_u32(const void* p) {
    uint32_t a;
    asm("{ .reg .u64 t; cvta.to.shared.u64 t, %1; cvt.u32.u64 %0, t; }"
        : "=r"(a) : "l"(p));
    return a;
}
__device__ __forceinline__ void ldsm4(uint32_t* r, uint32_t addr) {
    asm volatile("ldmatrix.sync.aligned.m8n8.x4.shared.b16 {%0,%1,%2,%3}, [%4];"
                 : "=r"(r[0]), "=r"(r[1]), "=r"(r[2]), "=r"(r[3]) : "r"(addr));
}
__device__ __forceinline__ void ldsm4t(uint32_t* r, uint32_t addr) {
    asm volatile("ldmatrix.sync.aligned.m8n8.x4.trans.shared.b16 {%0,%1,%2,%3}, [%4];"
                 : "=r"(r[0]), "=r"(r[1]), "=r"(r[2]), "=r"(r[3]) : "r"(addr));
}
__device__ __forceinline__ void mma_f16(float* d, const uint32_t* a, const uint32_t* b) {
    asm volatile(
        "mma.sync.aligned.m16n8k16.row.col.f32.f16.f16.f32 "
        "{%0,%1,%2,%3}, {%4,%5,%6,%7}, {%8,%9}, {%0,%1,%2,%3};"
        : "+f"(d[0]), "+f"(d[1]), "+f"(d[2]), "+f"(d[3])
        : "r"(a[0]), "r"(a[1]), "r"(a[2]), "r"(a[3]), "r"(b[0]), "r"(b[1]));
}
__device__ __forceinline__ void cp16(uint32_t dst, const void* src) {
    asm volatile("cp.async.cg.shared.global [%0], [%1], 16;" :: "r"(dst), "l"(src));
}
__device__ __forceinline__ void cp_commit() {
    asm volatile("cp.async.commit_group;" ::: "memory");
}
template<int N>
__device__ __forceinline__ void cp_wait() {
    asm volatile("cp.async.wait_group %0;" :: "n"(N) : "memory");
}

// ---------------- main GEMM kernel ----------------
// CTA 128x128, BK=64, warp tile 64x32, 2 CTAs/SM, fp16 in / fp32 accum.
// A-fragment double-buffered across the 4 kh sub-steps.
// ATR=1: A stored K-major [k][m] (dispatch mask); smem uses B-style layout + ldsm.trans.
// Two-level z indexing: off = (z/zMod)*s1 + (z%zMod)*s2; bias indexed by zr.
// OUTM: 0 = fp32 out, 2 = single f16 out.
template<int ATR, int OUTM, bool GELU_, bool BIAS_>
__global__ __launch_bounds__(THREADS, 2)
void moe_gemm(const f16* __restrict__ Ab, const f16* __restrict__ Bb,
              float* __restrict__ Cf, f16* __restrict__ Ch,
              const float* __restrict__ biasBase,
              int lda, int ldb, int ldc, int KT, int zMod,
              long long sA1, long long sA2, long long sB1, long long sB2,
              long long sC1, long long sC2, long long sBias2)
{
    extern __shared__ char smem[];
    const int tid  = threadIdx.x;
    const int lane = tid & 31;
    const int wid  = tid >> 5;
    const int wm   = (wid & 1) * 64;
    const int wn   = (wid >> 1) * 32;

    const int z = blockIdx.z;
    const int zq = z / zMod, zr = z % zMod;
    const f16* A = Ab + zq * sA1 + zr * sA2;
    const f16* B = Bb + zq * sB1 + zr * sB2;
    const long long coff = zq * sC1 + zr * sC2;
    const float* bias = BIAS_ ? biasBase + zr * sBias2 : nullptr;

    const int m0 = blockIdx.y * BM;
    const int n0 = blockIdx.x * BN;
    const uint32_t sbase = smem_u32(smem);

    float acc[4][4][4];
#pragma unroll
    for (int i = 0; i < 4; i++)
#pragma unroll
        for (int j = 0; j < 4; j++)
#pragma unroll
            for (int c = 0; c < 4; c++) acc[i][j][c] = 0.f;

    auto issue = [&](int it) {
        if (it < KT) {
            const uint32_t st = sbase + (it % NSTG) * STAGE;
            const int k0 = it * BK;
#pragma unroll
            for (int i = 0; i < 4; i++) {
                int c = tid + i * THREADS;          // 1024 chunks A
                if (ATR) {
                    int k = c >> 4, mc = c & 15;    // gmem row k, 16B m-chunk
                    cp16(st + b_off(k, mc),
                         A + (size_t)(k0 + k) * lda + m0 + mc * 8);
                } else {
                    int m = c >> 3, kc = c & 7;
                    cp16(st + a_off(m, kc),
                         A + (size_t)(m0 + m) * lda + k0 + kc * 8);
                }
            }
#pragma unroll
            for (int i = 0; i < 4; i++) {
                int c = tid + i * THREADS;          // 1024 chunks B
                int k = c >> 4, nc = c & 15;
                cp16(st + OFF_B + b_off(k, nc),
                     B + (size_t)(k0 + k) * ldb + n0 + nc * 8);
            }
        }
        cp_commit();
    };

    issue(0); issue(1);

    for (int it = 0; it < KT; ++it) {
        cp_wait<1>();
        __syncthreads();
        issue(it + 2);

        const uint32_t cur = sbase + (it % NSTG) * STAGE;

        auto loadA = [&](int kh, uint32_t (*ar)[4]) {
#pragma unroll
            for (int mf = 0; mf < 4; mf++) {
                if (ATR) {
                    int k = kh * 16 + (lane >> 4) * 8 + (lane & 7);
                    int mchunk = ((wm + mf * 16) >> 3) + ((lane >> 3) & 1);
                    ldsm4t(ar[mf], cur + b_off(k, mchunk));
                } else {
                    int row = wm + mf * 16 + (lane & 15);
                    int chunk = kh * 2 + (lane >> 4);
                    ldsm4(ar[mf], cur + a_off(row, chunk));
                }
            }
        };

        uint32_t arbuf[2][4][4];
        loadA(0, arbuf[0]);
#pragma unroll
        for (int kh = 0; kh < 4; kh++) {
            uint32_t br[2][4];
#pragma unroll
            for (int nb = 0; nb < 2; nb++) {
                int k = kh * 16 + ((lane >> 3) & 1) * 8 + (lane & 7);
                int nchunk = ((wn + nb * 16) >> 3) + (lane >> 4);
                ldsm4t(br[nb], cur + OFF_B + b_off(k, nchunk));
            }
            if (kh < 3) loadA(kh + 1, arbuf[(kh + 1) & 1]);
            uint32_t (*ar)[4] = arbuf[kh & 1];
#pragma unroll
            for (int mf = 0; mf < 4; mf++)
#pragma unroll
                for (int nf = 0; nf < 4; nf++)
                    mma_f16(acc[mf][nf], ar[mf], &br[nf >> 1][(nf & 1) * 2]);
        }
    }

    // ---- epilogue ----
    const int g = lane >> 2, t = lane & 3;
#pragma unroll
    for (int mf = 0; mf < 4; mf++) {
#pragma unroll
        for (int nf = 0; nf < 4; nf++) {
            int row = m0 + wm + mf * 16 + g;
            int col = n0 + wn + nf * 8 + t * 2;
            float v0 = acc[mf][nf][0], v1 = acc[mf][nf][1];
            float v2 = acc[mf][nf][2], v3 = acc[mf][nf][3];
            if (BIAS_) {
                float2 bv = *reinterpret_cast<const float2*>(bias + col);
                v0 += bv.x; v1 += bv.y; v2 += bv.x; v3 += bv.y;
            }
            if (GELU_) {
                v0 = 0.5f * v0 * (1.0f + erff(v0 * 0.70710678118654752f));
                v1 = 0.5f * v1 * (1.0f + erff(v1 * 0.70710678118654752f));
                v2 = 0.5f * v2 * (1.0f + erff(v2 * 0.70710678118654752f));
                v3 = 0.5f * v3 * (1.0f + erff(v3 * 0.70710678118654752f));
            }
            size_t o0 = (size_t)(coff + (size_t)row * ldc + col);
            size_t o1 = (size_t)(coff + (size_t)(row + 8) * ldc + col);
            if (OUTM == 0) {
                *reinterpret_cast<float2*>(Cf + o0) = make_float2(v0, v1);
                *reinterpret_cast<float2*>(Cf + o1) = make_float2(v2, v3);
            } else {
                *reinterpret_cast<uint32_t*>(Ch + o0) = pack_h2(v0, v1);
                *reinterpret_cast<uint32_t*>(Ch + o1) = pack_h2(v2, v3);
            }
        }
    }
}

// ---------------- launcher ----------------
extern "C" void kernel_launch(void* const* d_in, const int* in_sizes, int n_in,
                              void* d_out, int out_size)
{
    const float* x     = (const float*)d_in[0];
    const float* dmask = (const float*)d_in[1];
    const float* comb  = (const float*)d_in[2];
    const float* w1    = (const float*)d_in[3];
    const float* b1    = (const float*)d_in[4];
    const float* w2f   = (const float*)d_in[5];
    const float* b2    = (const float*)d_in[6];
    float* out = (float*)d_out;

    f16 *dm, *cmb, *xs, *w1s, *w2s, *xd, *hh, *yy;
    cudaGetSymbolAddress((void**)&dm,  g_dm);
    cudaGetSymbolAddress((void**)&cmb, g_cmb);
    cudaGetSymbolAddress((void**)&xs,  g_x);
    cudaGetSymbolAddress((void**)&w1s, g_w1);
    cudaGetSymbolAddress((void**)&w2s, g_w2);
    cudaGetSymbolAddress((void**)&xd,  g_xd);
    cudaGetSymbolAddress((void**)&hh,  g_h);
    cudaGetSymbolAddress((void**)&yy,  g_y);

    cudaFuncSetAttribute(moe_gemm<1, 2, false, false>,
                         cudaFuncAttributeMaxDynamicSharedMemorySize, SMEM_TOTAL);
    cudaFuncSetAttribute(moe_gemm<0, 2, true,  true>,
                         cudaFuncAttributeMaxDynamicSharedMemorySize, SMEM_TOTAL);
    cudaFuncSetAttribute(moe_gemm<0, 2, false, false>,
                         cudaFuncAttributeMaxDynamicSharedMemorySize, SMEM_TOTAL);
    cudaFuncSetAttribute(moe_gemm<0, 0, false, true>,
                         cudaFuncAttributeMaxDynamicSharedMemorySize, SMEM_TOTAL);

    // ---- conversions (elementwise fp16, MLP-2 contiguous) ----
    {
        long long n4 = (long long)BDIM * TDIM * ECDIM / 4;
        conv_ew<<<conv_grid(n4), 256>>>(dmask, dm, n4);
        conv_ew<<<conv_grid(n4), 256>>>(comb, cmb, n4);
    }
    {
        long long n4 = (long long)BDIM * TDIM * DDIM / 4;
        conv_ew<<<conv_grid(n4), 256>>>(x, xs, n4);
    }
    {
        long long n4 = (long long)EDIM * DDIM * HEDIM / 4;
        conv_ew<<<conv_grid(n4), 256>>>(w1, w1s, n4);
        conv_ew<<<conv_grid(n4), 256>>>(w2f, w2s, n4);
    }

    // ---- K1: xd[b][EC][D] = dmask_b^T[EC][T] @ x[b][T][D]  (ATR) ----
    moe_gemm<1, 2, false, false>
        <<<dim3(DDIM / BN, ECDIM / BM, BDIM), THREADS, SMEM_TOTAL>>>(
        dm, xs, nullptr, xd, nullptr,
        ECDIM, DDIM, DDIM, TDIM / BK, /*zMod*/ 1,
        (long long)TDIM * ECDIM, 0, (long long)TDIM * DDIM, 0,
        (long long)ECDIM * DDIM, 0, 0);

    // ---- K2: h[b,e][C][HE] = gelu(xd_{b,e}[C][D] @ w1_e[D][HE] + b1_e) ----
    moe_gemm<0, 2, true, true>
        <<<dim3(HEDIM / BN, CDIM / BM, BDIM * EDIM), THREADS, SMEM_TOTAL>>>(
        xd, w1s, nullptr, hh, b1,
        DDIM, HEDIM, HEDIM, DDIM / BK, /*zMod*/ EDIM,
        (long long)EDIM * CDIM * DDIM, (long long)CDIM * DDIM,
        0, (long long)DDIM * HEDIM,
        (long long)EDIM * CDIM * HEDIM, (long long)CDIM * HEDIM,
        (long long)HEDIM);

    // ---- K3: y[b,e][C][O] = h_{b,e}[C][HE] @ w2_e[HE][O] ----
    moe_gemm<0, 2, false, false>
        <<<dim3(ODIM / BN, CDIM / BM, BDIM * EDIM), THREADS, SMEM_TOTAL>>>(
        hh, w2s, nullptr, yy, nullptr,
        HEDIM, ODIM, ODIM, HEDIM / BK, /*zMod*/ EDIM,
        (long long)EDIM * CDIM * HEDIM, (long long)CDIM * HEDIM,
        0, (long long)HEDIM * ODIM,
        (long long)EDIM * CDIM * ODIM, (long long)CDIM * ODIM,
        0);

    // ---- K4: out[b][T][O] = comb[b][T][EC] @ y[b][EC][O] + b2 ----
    moe_gemm<0, 0, false, true>
        <<<dim3(ODIM / BN, TDIM / BM, BDIM), THREADS, SMEM_TOTAL>>>(
        cmb, yy, out, nullptr, b2,
        ECDIM, ODIM, ODIM, ECDIM / BK, /*zMod*/ 1,
        (long long)TDIM * ECDIM, 0, (long long)ECDIM * ODIM, 0,
        (long long)TDIM * ODIM, 0, 0);
}